// round 5
// baseline (speedup 1.0000x reference)
#include <cuda_runtime.h>
#include <cuda_bf16.h>
#include <math.h>

// Problem constants
#define NODES 50000
#define EDGES 800000
#define GG    1002
#define DD    256
#define CC    20
#define BN_EPS 1e-5f

// ---------------- scratch (device globals; no runtime allocation) ----------
__device__ float g_bufA[NODES * DD];   // h0 / h2
__device__ float g_bufB[NODES * DD];   // t (pre-aggregation)
__device__ float g_bufC[NODES * DD];   // h1 / z
__device__ float g_dinv[NODES];
__device__ int   g_cnt[NODES];
__device__ int   g_ptr[NODES + 1];
__device__ int   g_fill[NODES];
__device__ int   g_srcs[EDGES];
__device__ float g_bnsum[DD];
__device__ float g_bnsumsq[DD];
__device__ int   g_is64;               // edge_index dtype flag

// ---------------- dtype detection ------------------------------------------
// If edge_index is int64 (little-endian, values < 2^31), every odd int32 word
// of the first 32 elements is zero. Random int32 edges make that impossible.
__global__ void detect_dtype_kernel(const int* __restrict__ data) {
    if (threadIdx.x == 0 && blockIdx.x == 0) {
        int is64 = 1;
        for (int i = 1; i < 64; i += 2)
            if (data[i] != 0) { is64 = 0; break; }
        g_is64 = is64;
    }
}

__device__ __forceinline__ int load_edge(const void* p, long idx) {
    if (g_is64) return (int)((const long long*)p)[idx];
    return ((const int*)p)[idx];
}

// ---------------- utility kernels ------------------------------------------
__global__ void zero_kernel() {
    int i = blockIdx.x * blockDim.x + threadIdx.x;
    for (; i < NODES; i += gridDim.x * blockDim.x) g_cnt[i] = 0;
    int t = blockIdx.x * blockDim.x + threadIdx.x;
    if (t < DD) { g_bnsum[t] = 0.f; g_bnsumsq[t] = 0.f; }
}

__global__ void count_edges_kernel(const void* __restrict__ edge_index) {
    int e = blockIdx.x * blockDim.x + threadIdx.x;
    if (e >= EDGES) return;
    int dst = load_edge(edge_index, (long)EDGES + e);
    if ((unsigned)dst >= NODES) return;          // defensive
    atomicAdd(&g_cnt[dst], 1);
}

__global__ void dinv_kernel() {
    int i = blockIdx.x * blockDim.x + threadIdx.x;
    if (i >= NODES) return;
    float deg = (float)g_cnt[i] + 1.0f;
    g_dinv[i] = rsqrtf(deg);
}

// single-block exclusive scan of g_cnt -> g_ptr / g_fill
__global__ void scan_kernel() {
    __shared__ int ssum[1024];
    const int CH = (NODES + 1023) / 1024;   // 49
    int t = threadIdx.x;
    int beg = t * CH;
    int s = 0;
    for (int i = 0; i < CH; i++) {
        int idx = beg + i;
        if (idx < NODES) s += g_cnt[idx];
    }
    ssum[t] = s;
    __syncthreads();
    for (int off = 1; off < 1024; off <<= 1) {
        int v = (t >= off) ? ssum[t - off] : 0;
        __syncthreads();
        ssum[t] += v;
        __syncthreads();
    }
    int run = ssum[t] - s;   // exclusive prefix of this thread's chunk
    for (int i = 0; i < CH; i++) {
        int idx = beg + i;
        if (idx < NODES) {
            g_ptr[idx]  = run;
            g_fill[idx] = run;
            run += g_cnt[idx];
        }
    }
    if (t == 1023) g_ptr[NODES] = ssum[1023];
}

__global__ void scatter_edges_kernel(const void* __restrict__ edge_index) {
    int e = blockIdx.x * blockDim.x + threadIdx.x;
    if (e >= EDGES) return;
    int src = load_edge(edge_index, e);
    int dst = load_edge(edge_index, (long)EDGES + e);
    if ((unsigned)src >= NODES || (unsigned)dst >= NODES) return;  // defensive
    int pos = atomicAdd(&g_fill[dst], 1);
    if ((unsigned)pos >= EDGES) return;                            // defensive
    g_srcs[pos] = src;
}

// ---------------- FP32 tiled GEMM: C = A[M,K] @ B[K,Nn] --------------------
#define BM 128
#define BN 128
#define BK 8
#define TM 8
#define TN 8

__global__ __launch_bounds__(256, 2)
void gemm_kernel(const float* __restrict__ A, const float* __restrict__ B,
                 float* __restrict__ Cm, int M, int K, int Nn) {
    __shared__ float As[BK][BM];
    __shared__ float Bs[BK][BN];
    int tid = threadIdx.x;                // 256 threads
    int tm = (tid / (BN / TN)) * TM;      // 0..120
    int tn = (tid % (BN / TN)) * TN;      // 0..120
    int m0 = blockIdx.y * BM;
    int n0 = blockIdx.x * BN;
    float acc[TM][TN] = {};

    for (int k0 = 0; k0 < K; k0 += BK) {
#pragma unroll
        for (int i = 0; i < 4; i++) {
            int idx = tid + i * 256;      // 0..1023
            int m = idx >> 3;
            int k = idx & 7;
            int gm = m0 + m, gk = k0 + k;
            As[k][m] = (gm < M && gk < K) ? A[(long)gm * K + gk] : 0.f;
        }
#pragma unroll
        for (int i = 0; i < 4; i++) {
            int idx = tid + i * 256;
            int k = idx >> 7;
            int n = idx & 127;
            int gk = k0 + k;
            Bs[k][n] = (gk < K) ? B[(long)gk * Nn + n0 + n] : 0.f;
        }
        __syncthreads();
#pragma unroll
        for (int k = 0; k < BK; k++) {
            float a[TM], b[TN];
#pragma unroll
            for (int i = 0; i < TM; i++) a[i] = As[k][tm + i];
#pragma unroll
            for (int j = 0; j < TN; j++) b[j] = Bs[k][tn + j];
#pragma unroll
            for (int i = 0; i < TM; i++)
#pragma unroll
                for (int j = 0; j < TN; j++) acc[i][j] += a[i] * b[j];
        }
        __syncthreads();
    }
#pragma unroll
    for (int i = 0; i < TM; i++) {
        int gm = m0 + tm + i;
        if (gm >= M) continue;
#pragma unroll
        for (int j = 0; j < TN; j++)
            Cm[(long)gm * Nn + n0 + tn + j] = acc[i][j];
    }
}

// ---------------- GCN aggregation ------------------------------------------
// out[i] = relu(dinv_i * sum_j dinv_j * t[j] + t[i]/deg_i + bias)
__global__ void aggregate_kernel(const float* __restrict__ t,
                                 const float* __restrict__ bias,
                                 float* __restrict__ out) {
    int i = blockIdx.x;
    int c = threadIdx.x;                  // 256 = DD
    int beg = g_ptr[i], end = g_ptr[i + 1];
    float acc = 0.f;
    for (int e = beg; e < end; e++) {
        int j = g_srcs[e];
        if ((unsigned)j >= NODES) continue;       // defensive
        acc += g_dinv[j] * t[(long)j * DD + c];
    }
    float di = g_dinv[i];
    float v = di * acc + di * di * t[(long)i * DD + c] + bias[c];
    out[(long)i * DD + c] = fmaxf(v, 0.f);
}

// ---------------- BatchNorm (train-mode batch stats) -----------------------
__global__ void bn_stats_kernel(const float* __restrict__ a,
                                const float* __restrict__ b1) {
    int c = threadIdx.x;                  // 256
    float b = b1[c];
    int rows_per = (NODES + gridDim.x - 1) / gridDim.x;
    int r0 = blockIdx.x * rows_per;
    int r1 = min(NODES, r0 + rows_per);
    float s = 0.f, s2 = 0.f;
    for (int r = r0; r < r1; r++) {
        float v = a[(long)r * DD + c] + b;
        s += v;
        s2 += v * v;
    }
    atomicAdd(&g_bnsum[c], s);
    atomicAdd(&g_bnsumsq[c], s2);
}

__global__ void bn_apply_kernel(const float* __restrict__ a,
                                const float* __restrict__ b1,
                                const float* __restrict__ gamma,
                                const float* __restrict__ beta,
                                float* __restrict__ z) {
    const float invN = 1.0f / (float)NODES;
    long total = (long)NODES * DD;
    for (long i = (long)blockIdx.x * blockDim.x + threadIdx.x; i < total;
         i += (long)gridDim.x * blockDim.x) {
        int c = (int)(i & (DD - 1));
        float mean = g_bnsum[c] * invN;
        float var  = g_bnsumsq[c] * invN - mean * mean;
        float v = (a[i] + b1[c] - mean) * rsqrtf(var + BN_EPS) * gamma[c] + beta[c];
        z[i] = fmaxf(v, 0.f);
    }
}

// ---------------- head: logits = z @ W2 + b2, softmax ----------------------
__global__ void head_kernel(const float* __restrict__ z,
                            const float* __restrict__ w2,
                            const float* __restrict__ b2,
                            float* __restrict__ out) {
    __shared__ float wt[CC * DD];         // transposed W2: wt[c*256 + k]
    __shared__ float bsh[CC];
    int tid = threadIdx.x;
    for (int i = tid; i < CC * DD; i += 256) {
        int c = i >> 8, k = i & 255;
        wt[i] = w2[k * CC + c];
    }
    if (tid < CC) bsh[tid] = b2[tid];
    __syncthreads();

    int warp = tid >> 5, lane = tid & 31;
    int r = blockIdx.x * 8 + warp;
    if (r >= NODES) return;

    float zv[8];
#pragma unroll
    for (int i = 0; i < 8; i++) zv[i] = z[(long)r * DD + lane + 32 * i];

    float lg[CC];
#pragma unroll
    for (int c = 0; c < CC; c++) {
        float p = 0.f;
#pragma unroll
        for (int i = 0; i < 8; i++) p += zv[i] * wt[c * DD + lane + 32 * i];
#pragma unroll
        for (int off = 16; off; off >>= 1) p += __shfl_xor_sync(0xffffffffu, p, off);
        lg[c] = p + bsh[c];               // all lanes hold the full sum
    }
    float mx = -1e30f;
#pragma unroll
    for (int c = 0; c < CC; c++) mx = fmaxf(mx, lg[c]);
    float se = 0.f;
#pragma unroll
    for (int c = 0; c < CC; c++) { lg[c] = expf(lg[c] - mx); se += lg[c]; }
    float inv = 1.0f / se;
    if (lane < CC) {
        float myv = 0.f;
#pragma unroll
        for (int c = 0; c < CC; c++) if (c == lane) myv = lg[c];
        out[(long)r * CC + lane] = myv * inv;
    }
}

// ---------------- launch ----------------------------------------------------
extern "C" void kernel_launch(void* const* d_in, const int* in_sizes, int n_in,
                              void* d_out, int out_size) {
    const float* x       = (const float*)d_in[0];
    const void*  edges   = d_in[1];                  // int32 or int64, detected
    const float* lin_w   = (const float*)d_in[2];
    const float* conv1_w = (const float*)d_in[3];
    const float* conv1_b = (const float*)d_in[4];
    const float* conv2_w = (const float*)d_in[5];
    const float* conv2_b = (const float*)d_in[6];
    const float* mlp1_w  = (const float*)d_in[7];
    const float* mlp1_b  = (const float*)d_in[8];
    const float* bn_g    = (const float*)d_in[9];
    const float* bn_b    = (const float*)d_in[10];
    const float* mlp2_w  = (const float*)d_in[11];
    const float* mlp2_b  = (const float*)d_in[12];
    float*       out     = (float*)d_out;

    float* h0 = nullptr; float* t = nullptr; float* h1 = nullptr;
    cudaGetSymbolAddress((void**)&h0, g_bufA);
    cudaGetSymbolAddress((void**)&t,  g_bufB);
    cudaGetSymbolAddress((void**)&h1, g_bufC);

    // graph structure prep
    detect_dtype_kernel<<<1, 32>>>((const int*)edges);
    zero_kernel<<<256, 256>>>();
    count_edges_kernel<<<(EDGES + 255) / 256, 256>>>(edges);
    dinv_kernel<<<(NODES + 255) / 256, 256>>>();
    scan_kernel<<<1, 1024>>>();
    scatter_edges_kernel<<<(EDGES + 255) / 256, 256>>>(edges);

    dim3 tgrid(DD / BN, (NODES + BM - 1) / BM);   // (2, 391)

    // encoder: h0 = x @ lin_w
    gemm_kernel<<<tgrid, 256>>>(x, lin_w, h0, NODES, GG, DD);

    // conv1
    gemm_kernel<<<tgrid, 256>>>(h0, conv1_w, t, NODES, DD, DD);
    aggregate_kernel<<<NODES, DD>>>(t, conv1_b, h1);

    // conv2 (output back into h0)
    gemm_kernel<<<tgrid, 256>>>(h1, conv2_w, t, NODES, DD, DD);
    aggregate_kernel<<<NODES, DD>>>(t, conv2_b, h0);

    // mlp1 + BN + relu -> h1
    gemm_kernel<<<tgrid, 256>>>(h0, mlp1_w, t, NODES, DD, DD);
    bn_stats_kernel<<<256, DD>>>(t, mlp1_b);
    bn_apply_kernel<<<2048, 256>>>(t, mlp1_b, bn_g, bn_b, h1);

    // head
    head_kernel<<<(NODES + 7) / 8, 256>>>(h1, mlp2_w, mlp2_b, out);
}

// round 10
// speedup vs baseline: 1.5215x; 1.5215x over previous
#include <cuda_runtime.h>
#include <cuda_bf16.h>
#include <math.h>
#include <stdint.h>

// Problem constants
#define NODES 50000
#define EDGES 800000
#define GG    1002
#define DD    256
#define CC    20
#define BN_EPS 1e-5f

// ---------------- scratch (device globals; no runtime allocation) ----------
__device__ float g_bufA[NODES * DD];   // h0 / h2
__device__ float g_bufB[NODES * DD];   // t (pre-aggregation)
__device__ float g_bufC[NODES * DD];   // h1 / z
__device__ float g_wt[DD * 1024];      // transposed, K-padded weight [256][Kpad]
__device__ float g_dinv[NODES];
__device__ int   g_cnt[NODES];
__device__ int   g_ptr[NODES + 1];
__device__ int   g_fill[NODES];
__device__ int   g_srcs[EDGES];
__device__ float g_bnsum[DD];
__device__ float g_bnsumsq[DD];
__device__ int   g_is64;               // edge_index dtype flag

// ======================= helpers ===========================================
__device__ __forceinline__ uint32_t smem_to_u32(const void* smem_ptr) {
    uint32_t addr;
    asm("{ .reg .u64 tmp; cvta.to.shared.u64 tmp, %1; cvt.u32.u64 %0, tmp; }"
        : "=r"(addr) : "l"(smem_ptr));
    return addr;
}

__device__ __forceinline__ void ldsm4(uint32_t r[4], uint32_t addr) {
    asm volatile("ldmatrix.sync.aligned.m8n8.x4.shared.b16 {%0,%1,%2,%3}, [%4];"
                 : "=r"(r[0]), "=r"(r[1]), "=r"(r[2]), "=r"(r[3]) : "r"(addr));
}

__device__ __forceinline__ void mma16816(float d[4], const uint32_t a[4],
                                         uint32_t b0, uint32_t b1) {
    asm volatile(
        "mma.sync.aligned.m16n8k16.row.col.f32.bf16.bf16.f32 "
        "{%0,%1,%2,%3}, {%4,%5,%6,%7}, {%8,%9}, {%0,%1,%2,%3};"
        : "+f"(d[0]), "+f"(d[1]), "+f"(d[2]), "+f"(d[3])
        : "r"(a[0]), "r"(a[1]), "r"(a[2]), "r"(a[3]), "r"(b0), "r"(b1));
}

// bf16 split: v = hi + lo (+ O(2^-18))
__device__ __forceinline__ void split2(float v0, float v1,
                                       uint32_t& hi, uint32_t& lo) {
    __nv_bfloat16 h0 = __float2bfloat16_rn(v0);
    __nv_bfloat16 h1 = __float2bfloat16_rn(v1);
    float r0 = v0 - __bfloat162float(h0);
    float r1 = v1 - __bfloat162float(h1);
    __nv_bfloat16 l0 = __float2bfloat16_rn(r0);
    __nv_bfloat16 l1 = __float2bfloat16_rn(r1);
    hi = (uint32_t)__bfloat16_as_ushort(h0) | ((uint32_t)__bfloat16_as_ushort(h1) << 16);
    lo = (uint32_t)__bfloat16_as_ushort(l0) | ((uint32_t)__bfloat16_as_ushort(l1) << 16);
}

// ======================= split-bf16 mma.sync GEMM ==========================
// C[M,256] = A[M,K] @ W[K,256]; Bt = W^T zero-padded to [256][Kpad].
// CTA tile 128x128, 8 warps of 32x64, BK=32, 2-stage SMEM pipeline.
#define GBK 32
#define SROW 40                         // smem row stride in bf16 elements
#define AHI_OFF 0
#define ALO_OFF 10240
#define BHI_OFF 20480
#define BLO_OFF 30720
#define STG_BYTES 40960
#define GEMM_SMEM (2 * STG_BYTES)       // 81920

__global__ void __launch_bounds__(256, 1)
gemm_tc_kernel(const float* __restrict__ A, const float* __restrict__ Bt,
               float* __restrict__ Cm, int M, int K, int Kpad) {
    extern __shared__ char smem[];
    const uint32_t smem_base = smem_to_u32(smem);
    const int tid  = threadIdx.x;
    const int lane = tid & 31;
    const int wid  = tid >> 5;
    const int wm = (wid & 3) * 32;      // warp m-offset in tile
    const int wn = (wid >> 2) * 64;     // warp n-offset in tile
    const int m0 = blockIdx.y * 128;
    const int n0 = blockIdx.x * 128;

    const int NC = Kpad / GBK;

    // staging: each thread owns one (row, k-half) of both A and B tiles
    const int srow = tid >> 1;
    const int skh  = (tid & 1) * 16;
    const int gm   = m0 + srow;
    const float* arow = A  + (size_t)gm * K;
    const float* brow = Bt + (size_t)(n0 + srow) * Kpad;

    float2 ra[8], rb[8];
    float acc[2][8][4];
#pragma unroll
    for (int i = 0; i < 2; i++)
#pragma unroll
        for (int j = 0; j < 8; j++)
#pragma unroll
            for (int k = 0; k < 4; k++) acc[i][j][k] = 0.f;

    // ---- load chunk 0 ----
    {
        const int k0 = 0;
#pragma unroll
        for (int i = 0; i < 8; i++) {
            int kk = k0 + skh + 2 * i;
            ra[i] = (gm < M && kk < K) ? *(const float2*)(arow + kk)
                                       : make_float2(0.f, 0.f);
            rb[i] = *(const float2*)(brow + kk);
        }
    }
    // ---- store chunk 0 into stage 0 ----
    {
        char* base = smem;
        const uint32_t off0 = (uint32_t)(srow * SROW + skh) * 2;
#pragma unroll
        for (int i = 0; i < 8; i++) {
            uint32_t hi, lo;
            split2(ra[i].x, ra[i].y, hi, lo);
            *(uint32_t*)(base + AHI_OFF + off0 + 4 * i) = hi;
            *(uint32_t*)(base + ALO_OFF + off0 + 4 * i) = lo;
            split2(rb[i].x, rb[i].y, hi, lo);
            *(uint32_t*)(base + BHI_OFF + off0 + 4 * i) = hi;
            *(uint32_t*)(base + BLO_OFF + off0 + 4 * i) = lo;
        }
    }
    __syncthreads();

    for (int c = 0; c < NC; c++) {
        // ---- prefetch chunk c+1 into registers ----
        if (c + 1 < NC) {
            const int k0 = (c + 1) * GBK;
#pragma unroll
            for (int i = 0; i < 8; i++) {
                int kk = k0 + skh + 2 * i;
                ra[i] = (gm < M && kk < K) ? *(const float2*)(arow + kk)
                                           : make_float2(0.f, 0.f);
                rb[i] = *(const float2*)(brow + kk);
            }
        }

        // ---- compute chunk c from stage c&1 ----
        {
            const uint32_t stg = smem_base + (uint32_t)(c & 1) * STG_BYTES;
#pragma unroll
            for (int ks = 0; ks < 2; ks++) {
                const int koff = ks * 16 + ((lane >> 4) << 3);
                uint32_t ahi[2][4], alo[2][4];
#pragma unroll
                for (int tm = 0; tm < 2; tm++) {
                    uint32_t ro = (uint32_t)((wm + tm * 16 + (lane & 15)) * SROW + koff) * 2;
                    ldsm4(ahi[tm], stg + AHI_OFF + ro);
                    ldsm4(alo[tm], stg + ALO_OFF + ro);
                }
                uint32_t bhi[4][4], blo[4][4];
#pragma unroll
                for (int pn = 0; pn < 4; pn++) {
                    uint32_t ro = (uint32_t)((wn + pn * 16 + (lane & 15)) * SROW + koff) * 2;
                    ldsm4(bhi[pn], stg + BHI_OFF + ro);
                    ldsm4(blo[pn], stg + BLO_OFF + ro);
                }
#pragma unroll
                for (int tm = 0; tm < 2; tm++) {
#pragma unroll
                    for (int tn = 0; tn < 8; tn++) {
                        const int pn = tn >> 1, sel = tn & 1;
                        mma16816(acc[tm][tn], ahi[tm], bhi[pn][sel], bhi[pn][sel + 2]);
                        mma16816(acc[tm][tn], ahi[tm], blo[pn][sel], blo[pn][sel + 2]);
                        mma16816(acc[tm][tn], alo[tm], bhi[pn][sel], bhi[pn][sel + 2]);
                    }
                }
            }
        }
        __syncthreads();

        // ---- store prefetched chunk into stage (c+1)&1 ----
        if (c + 1 < NC) {
            char* base = smem + ((c + 1) & 1) * STG_BYTES;
            const uint32_t off0 = (uint32_t)(srow * SROW + skh) * 2;
#pragma unroll
            for (int i = 0; i < 8; i++) {
                uint32_t hi, lo;
                split2(ra[i].x, ra[i].y, hi, lo);
                *(uint32_t*)(base + AHI_OFF + off0 + 4 * i) = hi;
                *(uint32_t*)(base + ALO_OFF + off0 + 4 * i) = lo;
                split2(rb[i].x, rb[i].y, hi, lo);
                *(uint32_t*)(base + BHI_OFF + off0 + 4 * i) = hi;
                *(uint32_t*)(base + BLO_OFF + off0 + 4 * i) = lo;
            }
            __syncthreads();
        }
    }

    // ---- epilogue: write acc to C ----
#pragma unroll
    for (int tm = 0; tm < 2; tm++) {
        int r0 = m0 + wm + tm * 16 + (lane >> 2);
        int cbase = n0 + wn + (lane & 3) * 2;
#pragma unroll
        for (int tn = 0; tn < 8; tn++) {
            int col = cbase + tn * 8;
            if (r0 < M)
                *(float2*)(Cm + (size_t)r0 * DD + col) =
                    make_float2(acc[tm][tn][0], acc[tm][tn][1]);
            if (r0 + 8 < M)
                *(float2*)(Cm + (size_t)(r0 + 8) * DD + col) =
                    make_float2(acc[tm][tn][2], acc[tm][tn][3]);
        }
    }
}

// weight transpose + zero-pad: W[K][256] -> g_wt[n][Kpad]
__global__ void prep_wt_kernel(const float* __restrict__ W, int K, int Kpad) {
    int i = blockIdx.x * blockDim.x + threadIdx.x;
    int total = DD * Kpad;
    if (i >= total) return;
    int n = i / Kpad, k = i - n * Kpad;
    g_wt[i] = (k < K) ? W[(size_t)k * DD + n] : 0.f;
}

// ---------------- dtype detection ------------------------------------------
__global__ void detect_dtype_kernel(const int* __restrict__ data) {
    if (threadIdx.x == 0 && blockIdx.x == 0) {
        int is64 = 1;
        for (int i = 1; i < 64; i += 2)
            if (data[i] != 0) { is64 = 0; break; }
        g_is64 = is64;
    }
}

__device__ __forceinline__ int load_edge(const void* p, long idx) {
    if (g_is64) return (int)((const long long*)p)[idx];
    return ((const int*)p)[idx];
}

// ---------------- utility kernels ------------------------------------------
__global__ void zero_kernel() {
    int i = blockIdx.x * blockDim.x + threadIdx.x;
    for (; i < NODES; i += gridDim.x * blockDim.x) g_cnt[i] = 0;
    int t = blockIdx.x * blockDim.x + threadIdx.x;
    if (t < DD) { g_bnsum[t] = 0.f; g_bnsumsq[t] = 0.f; }
}

__global__ void count_edges_kernel(const void* __restrict__ edge_index) {
    int e = blockIdx.x * blockDim.x + threadIdx.x;
    if (e >= EDGES) return;
    int dst = load_edge(edge_index, (long)EDGES + e);
    if ((unsigned)dst >= NODES) return;
    atomicAdd(&g_cnt[dst], 1);
}

__global__ void dinv_kernel() {
    int i = blockIdx.x * blockDim.x + threadIdx.x;
    if (i >= NODES) return;
    float deg = (float)g_cnt[i] + 1.0f;
    g_dinv[i] = rsqrtf(deg);
}

__global__ void scan_kernel() {
    __shared__ int ssum[1024];
    const int CH = (NODES + 1023) / 1024;
    int t = threadIdx.x;
    int beg = t * CH;
    int s = 0;
    for (int i = 0; i < CH; i++) {
        int idx = beg + i;
        if (idx < NODES) s += g_cnt[idx];
    }
    ssum[t] = s;
    __syncthreads();
    for (int off = 1; off < 1024; off <<= 1) {
        int v = (t >= off) ? ssum[t - off] : 0;
        __syncthreads();
        ssum[t] += v;
        __syncthreads();
    }
    int run = ssum[t] - s;
    for (int i = 0; i < CH; i++) {
        int idx = beg + i;
        if (idx < NODES) {
            g_ptr[idx]  = run;
            g_fill[idx] = run;
            run += g_cnt[idx];
        }
    }
    if (t == 1023) g_ptr[NODES] = ssum[1023];
}

__global__ void scatter_edges_kernel(const void* __restrict__ edge_index) {
    int e = blockIdx.x * blockDim.x + threadIdx.x;
    if (e >= EDGES) return;
    int src = load_edge(edge_index, e);
    int dst = load_edge(edge_index, (long)EDGES + e);
    if ((unsigned)src >= NODES || (unsigned)dst >= NODES) return;
    int pos = atomicAdd(&g_fill[dst], 1);
    if ((unsigned)pos >= EDGES) return;
    g_srcs[pos] = src;
}

// ---------------- GCN aggregation ------------------------------------------
__global__ void aggregate_kernel(const float* __restrict__ t,
                                 const float* __restrict__ bias,
                                 float* __restrict__ out) {
    int i = blockIdx.x;
    int c = threadIdx.x;                  // 256 = DD
    int beg = g_ptr[i], end = g_ptr[i + 1];
    float acc = 0.f;
    for (int e = beg; e < end; e++) {
        int j = g_srcs[e];
        if ((unsigned)j >= NODES) continue;
        acc += g_dinv[j] * t[(size_t)j * DD + c];
    }
    float di = g_dinv[i];
    float v = di * acc + di * di * t[(size_t)i * DD + c] + bias[c];
    out[(size_t)i * DD + c] = fmaxf(v, 0.f);
}

// ---------------- BatchNorm ------------------------------------------------
__global__ void bn_stats_kernel(const float* __restrict__ a,
                                const float* __restrict__ b1) {
    int c = threadIdx.x;
    float b = b1[c];
    int rows_per = (NODES + gridDim.x - 1) / gridDim.x;
    int r0 = blockIdx.x * rows_per;
    int r1 = min(NODES, r0 + rows_per);
    float s = 0.f, s2 = 0.f;
    for (int r = r0; r < r1; r++) {
        float v = a[(size_t)r * DD + c] + b;
        s += v;
        s2 += v * v;
    }
    atomicAdd(&g_bnsum[c], s);
    atomicAdd(&g_bnsumsq[c], s2);
}

__global__ void bn_apply_kernel(const float* __restrict__ a,
                                const float* __restrict__ b1,
                                const float* __restrict__ gamma,
                                const float* __restrict__ beta,
                                float* __restrict__ z) {
    const float invN = 1.0f / (float)NODES;
    long total = (long)NODES * DD;
    for (long i = (long)blockIdx.x * blockDim.x + threadIdx.x; i < total;
         i += (long)gridDim.x * blockDim.x) {
        int c = (int)(i & (DD - 1));
        float mean = g_bnsum[c] * invN;
        float var  = g_bnsumsq[c] * invN - mean * mean;
        float v = (a[i] + b1[c] - mean) * rsqrtf(var + BN_EPS) * gamma[c] + beta[c];
        z[i] = fmaxf(v, 0.f);
    }
}

// ---------------- head -----------------------------------------------------
__global__ void head_kernel(const float* __restrict__ z,
                            const float* __restrict__ w2,
                            const float* __restrict__ b2,
                            float* __restrict__ out) {
    __shared__ float wt[CC * DD];
    __shared__ float bsh[CC];
    int tid = threadIdx.x;
    for (int i = tid; i < CC * DD; i += 256) {
        int c = i >> 8, k = i & 255;
        wt[i] = w2[k * CC + c];
    }
    if (tid < CC) bsh[tid] = b2[tid];
    __syncthreads();

    int warp = tid >> 5, lane = tid & 31;
    int r = blockIdx.x * 8 + warp;
    if (r >= NODES) return;

    float zv[8];
#pragma unroll
    for (int i = 0; i < 8; i++) zv[i] = z[(size_t)r * DD + lane + 32 * i];

    float lg[CC];
#pragma unroll
    for (int c = 0; c < CC; c++) {
        float p = 0.f;
#pragma unroll
        for (int i = 0; i < 8; i++) p += zv[i] * wt[c * DD + lane + 32 * i];
#pragma unroll
        for (int off = 16; off; off >>= 1) p += __shfl_xor_sync(0xffffffffu, p, off);
        lg[c] = p + bsh[c];
    }
    float mx = -1e30f;
#pragma unroll
    for (int c = 0; c < CC; c++) mx = fmaxf(mx, lg[c]);
    float se = 0.f;
#pragma unroll
    for (int c = 0; c < CC; c++) { lg[c] = expf(lg[c] - mx); se += lg[c]; }
    float inv = 1.0f / se;
    if (lane < CC) {
        float myv = 0.f;
#pragma unroll
        for (int c = 0; c < CC; c++) if (c == lane) myv = lg[c];
        out[(size_t)r * CC + lane] = myv * inv;
    }
}

// ---------------- launch ----------------------------------------------------
extern "C" void kernel_launch(void* const* d_in, const int* in_sizes, int n_in,
                              void* d_out, int out_size) {
    const float* x       = (const float*)d_in[0];
    const void*  edges   = d_in[1];
    const float* lin_w   = (const float*)d_in[2];
    const float* conv1_w = (const float*)d_in[3];
    const float* conv1_b = (const float*)d_in[4];
    const float* conv2_w = (const float*)d_in[5];
    const float* conv2_b = (const float*)d_in[6];
    const float* mlp1_w  = (const float*)d_in[7];
    const float* mlp1_b  = (const float*)d_in[8];
    const float* bn_g    = (const float*)d_in[9];
    const float* bn_b    = (const float*)d_in[10];
    const float* mlp2_w  = (const float*)d_in[11];
    const float* mlp2_b  = (const float*)d_in[12];
    float*       out     = (float*)d_out;

    float* h0 = nullptr; float* t = nullptr; float* h1 = nullptr; float* wt = nullptr;
    cudaGetSymbolAddress((void**)&h0, g_bufA);
    cudaGetSymbolAddress((void**)&t,  g_bufB);
    cudaGetSymbolAddress((void**)&h1, g_bufC);
    cudaGetSymbolAddress((void**)&wt, g_wt);

    cudaFuncSetAttribute(gemm_tc_kernel,
                         cudaFuncAttributeMaxDynamicSharedMemorySize, GEMM_SMEM);

    // graph structure prep
    detect_dtype_kernel<<<1, 32>>>((const int*)edges);
    zero_kernel<<<256, 256>>>();
    count_edges_kernel<<<(EDGES + 255) / 256, 256>>>(edges);
    dinv_kernel<<<(NODES + 255) / 256, 256>>>();
    scan_kernel<<<1, 1024>>>();
    scatter_edges_kernel<<<(EDGES + 255) / 256, 256>>>(edges);

    dim3 ggrid(2, (NODES + 127) / 128);   // (2, 391)

    // encoder: h0 = x @ lin_w    (K = 1002, Kpad = 1024)
    prep_wt_kernel<<<(DD * 1024 + 255) / 256, 256>>>(lin_w, GG, 1024);
    gemm_tc_kernel<<<ggrid, 256, GEMM_SMEM>>>(x, wt, h0, NODES, GG, 1024);

    // conv1: t = h0 @ conv1_w; aggregate -> h1
    prep_wt_kernel<<<(DD * DD + 255) / 256, 256>>>(conv1_w, DD, DD);
    gemm_tc_kernel<<<ggrid, 256, GEMM_SMEM>>>(h0, wt, t, NODES, DD, DD);
    aggregate_kernel<<<NODES, DD>>>(t, conv1_b, h1);

    // conv2: t = h1 @ conv2_w; aggregate -> h0
    prep_wt_kernel<<<(DD * DD + 255) / 256, 256>>>(conv2_w, DD, DD);
    gemm_tc_kernel<<<ggrid, 256, GEMM_SMEM>>>(h1, wt, t, NODES, DD, DD);
    aggregate_kernel<<<NODES, DD>>>(t, conv2_b, h0);

    // mlp1 + BN + relu -> h1
    prep_wt_kernel<<<(DD * DD + 255) / 256, 256>>>(mlp1_w, DD, DD);
    gemm_tc_kernel<<<ggrid, 256, GEMM_SMEM>>>(h0, wt, t, NODES, DD, DD);
    bn_stats_kernel<<<256, DD>>>(t, mlp1_b);
    bn_apply_kernel<<<2048, 256>>>(t, mlp1_b, bn_g, bn_b, h1);

    // head
    head_kernel<<<(NODES + 7) / 8, 256>>>(h1, mlp2_w, mlp2_b, out);
}

// round 11
// speedup vs baseline: 1.6763x; 1.1017x over previous
#include <cuda_runtime.h>
#include <cuda_bf16.h>
#include <math.h>
#include <stdint.h>

// Problem constants
#define NODES 50000
#define EDGES 800000
#define GG    1002
#define DD    256
#define CC    20
#define BN_EPS 1e-5f
#define MPAD  50048                     // 391 * 128

// ---------------- scratch (device globals; no runtime allocation) ----------
__device__ float          g_bufB[NODES * DD];        // t (pre-aggregation)
__device__ float          g_bufC[NODES * DD];        // z
__device__ __nv_bfloat16  g_ahi[(size_t)MPAD * 1024];
__device__ __nv_bfloat16  g_alo[(size_t)MPAD * 1024];
__device__ __nv_bfloat16  g_bhi[(size_t)MPAD * DD];  // activation hi
__device__ __nv_bfloat16  g_blo[(size_t)MPAD * DD];  // activation lo
__device__ __nv_bfloat16  g_chi[(size_t)MPAD * DD];  // activation hi (ping)
__device__ __nv_bfloat16  g_clo[(size_t)MPAD * DD];  // activation lo (ping)
__device__ __nv_bfloat16  g_wthi[DD * 1024];
__device__ __nv_bfloat16  g_wtlo[DD * 1024];
__device__ float g_dinv[NODES];
__device__ int   g_cnt[NODES];
__device__ int   g_ptr[NODES + 1];
__device__ int   g_fill[NODES];
__device__ int   g_srcs[EDGES];
__device__ float g_bnsum[DD];
__device__ float g_bnsumsq[DD];
__device__ int   g_is64;

// ======================= helpers ===========================================
__device__ __forceinline__ uint32_t smem_to_u32(const void* smem_ptr) {
    uint32_t addr;
    asm("{ .reg .u64 tmp; cvta.to.shared.u64 tmp, %1; cvt.u32.u64 %0, tmp; }"
        : "=r"(addr) : "l"(smem_ptr));
    return addr;
}

__device__ __forceinline__ void ldsm4(uint32_t r[4], uint32_t addr) {
    asm volatile("ldmatrix.sync.aligned.m8n8.x4.shared.b16 {%0,%1,%2,%3}, [%4];"
                 : "=r"(r[0]), "=r"(r[1]), "=r"(r[2]), "=r"(r[3]) : "r"(addr));
}

__device__ __forceinline__ void mma16816(float d[4], const uint32_t a[4],
                                         uint32_t b0, uint32_t b1) {
    asm volatile(
        "mma.sync.aligned.m16n8k16.row.col.f32.bf16.bf16.f32 "
        "{%0,%1,%2,%3}, {%4,%5,%6,%7}, {%8,%9}, {%0,%1,%2,%3};"
        : "+f"(d[0]), "+f"(d[1]), "+f"(d[2]), "+f"(d[3])
        : "r"(a[0]), "r"(a[1]), "r"(a[2]), "r"(a[3]), "r"(b0), "r"(b1));
}

__device__ __forceinline__ void cpasync16(uint32_t dst, const void* src) {
    asm volatile("cp.async.cg.shared.global [%0], [%1], 16;"
                 :: "r"(dst), "l"(src) : "memory");
}
#define CP_COMMIT() asm volatile("cp.async.commit_group;" ::: "memory")
#define CP_WAIT2()  asm volatile("cp.async.wait_group 2;"  ::: "memory")

// bf16 split: v = hi + lo (+ O(2^-18))
__device__ __forceinline__ void split2(float v0, float v1,
                                       uint32_t& hi, uint32_t& lo) {
    __nv_bfloat16 h0 = __float2bfloat16_rn(v0);
    __nv_bfloat16 h1 = __float2bfloat16_rn(v1);
    float r0 = v0 - __bfloat162float(h0);
    float r1 = v1 - __bfloat162float(h1);
    __nv_bfloat16 l0 = __float2bfloat16_rn(r0);
    __nv_bfloat16 l1 = __float2bfloat16_rn(r1);
    hi = (uint32_t)__bfloat16_as_ushort(h0) | ((uint32_t)__bfloat16_as_ushort(h1) << 16);
    lo = (uint32_t)__bfloat16_as_ushort(l0) | ((uint32_t)__bfloat16_as_ushort(l1) << 16);
}

// ======================= split-bf16 mma.sync GEMM ==========================
// C[M,256] = (Ahi+Alo)[M,Kpad] @ (Whi+Wlo)^T; operands pre-split bf16.
// CTA tile 128x128, 8 warps of 32x64, BK=32, 4-stage cp.async pipeline.
#define GBK 32
#define RSTR 80                         // padded row stride, bytes
#define AHI_OFF 0
#define ALO_OFF 10240
#define BHI_OFF 20480
#define BLO_OFF 30720
#define STG_BYTES 40960
#define GEMM_SMEM (4 * STG_BYTES)       // 163840

__global__ void __launch_bounds__(256, 1)
gemm_tc_kernel(const __nv_bfloat16* __restrict__ Ahi,
               const __nv_bfloat16* __restrict__ Alo,
               int Kpad, float* __restrict__ Cf,
               __nv_bfloat16* __restrict__ Ohi, __nv_bfloat16* __restrict__ Olo,
               int M, int mode) {               // mode 0: fp32 out; 1: split out
    extern __shared__ char smem[];
    const uint32_t smem_base = smem_to_u32(smem);
    const int tid  = threadIdx.x;
    const int lane = tid & 31;
    const int wid  = tid >> 5;
    const int wm = (wid & 3) * 32;
    const int wn = (wid >> 2) * 64;
    const int m0 = blockIdx.y * 128;
    const int n0 = blockIdx.x * 128;
    const int NC = Kpad / GBK;

    const __nv_bfloat16* Bhi = g_wthi;
    const __nv_bfloat16* Blo = g_wtlo;

    // per-thread cp.async assignment: 2 chunks of 16B per array per stage
    const int r0i = (tid * 2) >> 2;          // row of first chunk
    const int c0i = (tid * 2) & 3;           // 16B-chunk col of first chunk
    const int r1i = (tid * 2 + 1) >> 2;
    const int c1i = (tid * 2 + 1) & 3;

    float acc[2][8][4];
#pragma unroll
    for (int i = 0; i < 2; i++)
#pragma unroll
        for (int j = 0; j < 8; j++)
#pragma unroll
            for (int k = 0; k < 4; k++) acc[i][j][k] = 0.f;

#define ISSUE_STAGE(slot, k0)                                                   \
    do {                                                                        \
        const uint32_t stg_ = smem_base + (uint32_t)(slot) * STG_BYTES;         \
        const size_t ab = (size_t)(m0 + r0i) * Kpad + (k0) + c0i * 8;           \
        const size_t ab2 = (size_t)(m0 + r1i) * Kpad + (k0) + c1i * 8;          \
        const size_t bb = (size_t)(n0 + r0i) * Kpad + (k0) + c0i * 8;           \
        const size_t bb2 = (size_t)(n0 + r1i) * Kpad + (k0) + c1i * 8;          \
        const uint32_t d0 = (uint32_t)(r0i * RSTR + c0i * 16);                  \
        const uint32_t d1 = (uint32_t)(r1i * RSTR + c1i * 16);                  \
        cpasync16(stg_ + AHI_OFF + d0, Ahi + ab);                               \
        cpasync16(stg_ + AHI_OFF + d1, Ahi + ab2);                              \
        cpasync16(stg_ + ALO_OFF + d0, Alo + ab);                               \
        cpasync16(stg_ + ALO_OFF + d1, Alo + ab2);                              \
        cpasync16(stg_ + BHI_OFF + d0, Bhi + bb);                               \
        cpasync16(stg_ + BHI_OFF + d1, Bhi + bb2);                              \
        cpasync16(stg_ + BLO_OFF + d0, Blo + bb);                               \
        cpasync16(stg_ + BLO_OFF + d1, Blo + bb2);                              \
    } while (0)

    // prologue: fill 3 stages (NC >= 8 always)
    ISSUE_STAGE(0, 0);  CP_COMMIT();
    ISSUE_STAGE(1, 32); CP_COMMIT();
    ISSUE_STAGE(2, 64); CP_COMMIT();

    for (int c = 0; c < NC; c++) {
        CP_WAIT2();
        __syncthreads();
        if (c + 3 < NC) ISSUE_STAGE((c + 3) & 3, (c + 3) * GBK);
        CP_COMMIT();

        const uint32_t stg = smem_base + (uint32_t)(c & 3) * STG_BYTES;
#pragma unroll
        for (int ks = 0; ks < 2; ks++) {
            const int koff = (ks * 16 + ((lane >> 4) << 3)) * 2;   // bytes
            uint32_t ahi[2][4], alo[2][4];
#pragma unroll
            for (int tm = 0; tm < 2; tm++) {
                uint32_t ro = (uint32_t)((wm + tm * 16 + (lane & 15)) * RSTR + koff);
                ldsm4(ahi[tm], stg + AHI_OFF + ro);
                ldsm4(alo[tm], stg + ALO_OFF + ro);
            }
            uint32_t bhi[4][4], blo[4][4];
#pragma unroll
            for (int pn = 0; pn < 4; pn++) {
                uint32_t ro = (uint32_t)((wn + pn * 16 + (lane & 15)) * RSTR + koff);
                ldsm4(bhi[pn], stg + BHI_OFF + ro);
                ldsm4(blo[pn], stg + BLO_OFF + ro);
            }
#pragma unroll
            for (int tm = 0; tm < 2; tm++) {
#pragma unroll
                for (int tn = 0; tn < 8; tn++) {
                    const int pn = tn >> 1, sel = tn & 1;
                    mma16816(acc[tm][tn], ahi[tm], bhi[pn][sel], bhi[pn][sel + 2]);
                    mma16816(acc[tm][tn], ahi[tm], blo[pn][sel], blo[pn][sel + 2]);
                    mma16816(acc[tm][tn], alo[tm], bhi[pn][sel], bhi[pn][sel + 2]);
                }
            }
        }
    }

    // ---- epilogue ----
#pragma unroll
    for (int tm = 0; tm < 2; tm++) {
        int r0 = m0 + wm + tm * 16 + (lane >> 2);
        int cbase = n0 + wn + (lane & 3) * 2;
#pragma unroll
        for (int tn = 0; tn < 8; tn++) {
            int col = cbase + tn * 8;
            if (mode == 0) {
                if (r0 < M)
                    *(float2*)(Cf + (size_t)r0 * DD + col) =
                        make_float2(acc[tm][tn][0], acc[tm][tn][1]);
                if (r0 + 8 < M)
                    *(float2*)(Cf + (size_t)(r0 + 8) * DD + col) =
                        make_float2(acc[tm][tn][2], acc[tm][tn][3]);
            } else {
                uint32_t hi, lo;
                if (r0 < M) {
                    split2(acc[tm][tn][0], acc[tm][tn][1], hi, lo);
                    *(uint32_t*)(Ohi + (size_t)r0 * DD + col) = hi;
                    *(uint32_t*)(Olo + (size_t)r0 * DD + col) = lo;
                }
                if (r0 + 8 < M) {
                    split2(acc[tm][tn][2], acc[tm][tn][3], hi, lo);
                    *(uint32_t*)(Ohi + (size_t)(r0 + 8) * DD + col) = hi;
                    *(uint32_t*)(Olo + (size_t)(r0 + 8) * DD + col) = lo;
                }
            }
        }
    }
}

// split x into g_ahi/g_alo, padded [MPAD x 1024]
__global__ void split_x_kernel(const float* __restrict__ X) {
    long i = (long)blockIdx.x * blockDim.x + threadIdx.x;
    const long total = (long)MPAD * 512;       // u32 pairs
    if (i >= total) return;
    int row = (int)(i >> 9);
    int kp = ((int)(i & 511)) * 2;
    float v0 = 0.f, v1 = 0.f;
    if (row < NODES) {
        if (kp < GG)     v0 = X[(size_t)row * GG + kp];
        if (kp + 1 < GG) v1 = X[(size_t)row * GG + kp + 1];
    }
    uint32_t hi, lo;
    split2(v0, v1, hi, lo);
    ((uint32_t*)g_ahi)[i] = hi;
    ((uint32_t*)g_alo)[i] = lo;
}

// W[K][256] -> g_wthi/g_wtlo [256][Kpad] (transposed, zero-padded, split)
__global__ void prep_wt_kernel(const float* __restrict__ W, int K, int Kpad) {
    int i = blockIdx.x * blockDim.x + threadIdx.x;
    int total = DD * (Kpad >> 1);
    if (i >= total) return;
    int n = i / (Kpad >> 1);
    int kp = (i - n * (Kpad >> 1)) * 2;
    float v0 = (kp < K)     ? W[(size_t)kp * DD + n]       : 0.f;
    float v1 = (kp + 1 < K) ? W[(size_t)(kp + 1) * DD + n] : 0.f;
    uint32_t hi, lo;
    split2(v0, v1, hi, lo);
    ((uint32_t*)g_wthi)[i] = hi;
    ((uint32_t*)g_wtlo)[i] = lo;
}

// ---------------- dtype detection ------------------------------------------
__global__ void detect_dtype_kernel(const int* __restrict__ data) {
    if (threadIdx.x == 0 && blockIdx.x == 0) {
        int is64 = 1;
        for (int i = 1; i < 64; i += 2)
            if (data[i] != 0) { is64 = 0; break; }
        g_is64 = is64;
    }
}

__device__ __forceinline__ int load_edge(const void* p, long idx) {
    if (g_is64) return (int)((const long long*)p)[idx];
    return ((const int*)p)[idx];
}

// ---------------- utility kernels ------------------------------------------
__global__ void zero_kernel() {
    int i = blockIdx.x * blockDim.x + threadIdx.x;
    for (; i < NODES; i += gridDim.x * blockDim.x) g_cnt[i] = 0;
    int t = blockIdx.x * blockDim.x + threadIdx.x;
    if (t < DD) { g_bnsum[t] = 0.f; g_bnsumsq[t] = 0.f; }
}

__global__ void count_edges_kernel(const void* __restrict__ edge_index) {
    int e = blockIdx.x * blockDim.x + threadIdx.x;
    if (e >= EDGES) return;
    int dst = load_edge(edge_index, (long)EDGES + e);
    if ((unsigned)dst >= NODES) return;
    atomicAdd(&g_cnt[dst], 1);
}

__global__ void dinv_kernel() {
    int i = blockIdx.x * blockDim.x + threadIdx.x;
    if (i >= NODES) return;
    float deg = (float)g_cnt[i] + 1.0f;
    g_dinv[i] = rsqrtf(deg);
}

__global__ void scan_kernel() {
    __shared__ int ssum[1024];
    const int CH = (NODES + 1023) / 1024;
    int t = threadIdx.x;
    int beg = t * CH;
    int s = 0;
    for (int i = 0; i < CH; i++) {
        int idx = beg + i;
        if (idx < NODES) s += g_cnt[idx];
    }
    ssum[t] = s;
    __syncthreads();
    for (int off = 1; off < 1024; off <<= 1) {
        int v = (t >= off) ? ssum[t - off] : 0;
        __syncthreads();
        ssum[t] += v;
        __syncthreads();
    }
    int run = ssum[t] - s;
    for (int i = 0; i < CH; i++) {
        int idx = beg + i;
        if (idx < NODES) {
            g_ptr[idx]  = run;
            g_fill[idx] = run;
            run += g_cnt[idx];
        }
    }
    if (t == 1023) g_ptr[NODES] = ssum[1023];
}

__global__ void scatter_edges_kernel(const void* __restrict__ edge_index) {
    int e = blockIdx.x * blockDim.x + threadIdx.x;
    if (e >= EDGES) return;
    int src = load_edge(edge_index, e);
    int dst = load_edge(edge_index, (long)EDGES + e);
    if ((unsigned)src >= NODES || (unsigned)dst >= NODES) return;
    int pos = atomicAdd(&g_fill[dst], 1);
    if ((unsigned)pos >= EDGES) return;
    g_srcs[pos] = src;
}

// ---------------- GCN aggregation (writes split bf16 activation) -----------
__global__ void aggregate_kernel(const float* __restrict__ t,
                                 const float* __restrict__ bias,
                                 __nv_bfloat16* __restrict__ ohi,
                                 __nv_bfloat16* __restrict__ olo) {
    int i = blockIdx.x;
    int c = threadIdx.x;                  // 256 = DD
    int beg = g_ptr[i], end = g_ptr[i + 1];
    float acc = 0.f;
    for (int e = beg; e < end; e++) {
        int j = g_srcs[e];
        if ((unsigned)j >= NODES) continue;
        acc += g_dinv[j] * t[(size_t)j * DD + c];
    }
    float di = g_dinv[i];
    float v = di * acc + di * di * t[(size_t)i * DD + c] + bias[c];
    v = fmaxf(v, 0.f);
    __nv_bfloat16 h = __float2bfloat16_rn(v);
    __nv_bfloat16 l = __float2bfloat16_rn(v - __bfloat162float(h));
    ohi[(size_t)i * DD + c] = h;
    olo[(size_t)i * DD + c] = l;
}

// ---------------- BatchNorm ------------------------------------------------
__global__ void bn_stats_kernel(const float* __restrict__ a,
                                const float* __restrict__ b1) {
    int c = threadIdx.x;
    float b = b1[c];
    int rows_per = (NODES + gridDim.x - 1) / gridDim.x;
    int r0 = blockIdx.x * rows_per;
    int r1 = min(NODES, r0 + rows_per);
    float s = 0.f, s2 = 0.f;
    for (int r = r0; r < r1; r++) {
        float v = a[(size_t)r * DD + c] + b;
        s += v;
        s2 += v * v;
    }
    atomicAdd(&g_bnsum[c], s);
    atomicAdd(&g_bnsumsq[c], s2);
}

__global__ void bn_apply_kernel(const float* __restrict__ a,
                                const float* __restrict__ b1,
                                const float* __restrict__ gamma,
                                const float* __restrict__ beta,
                                float* __restrict__ z) {
    const float invN = 1.0f / (float)NODES;
    long total = (long)NODES * DD;
    for (long i = (long)blockIdx.x * blockDim.x + threadIdx.x; i < total;
         i += (long)gridDim.x * blockDim.x) {
        int c = (int)(i & (DD - 1));
        float mean = g_bnsum[c] * invN;
        float var  = g_bnsumsq[c] * invN - mean * mean;
        float v = (a[i] + b1[c] - mean) * rsqrtf(var + BN_EPS) * gamma[c] + beta[c];
        z[i] = fmaxf(v, 0.f);
    }
}

// ---------------- head -----------------------------------------------------
__global__ void head_kernel(const float* __restrict__ z,
                            const float* __restrict__ w2,
                            const float* __restrict__ b2,
                            float* __restrict__ out) {
    __shared__ float wt[CC * DD];
    __shared__ float bsh[CC];
    int tid = threadIdx.x;
    for (int i = tid; i < CC * DD; i += 256) {
        int c = i >> 8, k = i & 255;
        wt[i] = w2[k * CC + c];
    }
    if (tid < CC) bsh[tid] = b2[tid];
    __syncthreads();

    int warp = tid >> 5, lane = tid & 31;
    int r = blockIdx.x * 8 + warp;
    if (r >= NODES) return;

    float zv[8];
#pragma unroll
    for (int i = 0; i < 8; i++) zv[i] = z[(size_t)r * DD + lane + 32 * i];

    float lg[CC];
#pragma unroll
    for (int c = 0; c < CC; c++) {
        float p = 0.f;
#pragma unroll
        for (int i = 0; i < 8; i++) p += zv[i] * wt[c * DD + lane + 32 * i];
#pragma unroll
        for (int off = 16; off; off >>= 1) p += __shfl_xor_sync(0xffffffffu, p, off);
        lg[c] = p + bsh[c];
    }
    float mx = -1e30f;
#pragma unroll
    for (int c = 0; c < CC; c++) mx = fmaxf(mx, lg[c]);
    float se = 0.f;
#pragma unroll
    for (int c = 0; c < CC; c++) { lg[c] = expf(lg[c] - mx); se += lg[c]; }
    float inv = 1.0f / se;
    if (lane < CC) {
        float myv = 0.f;
#pragma unroll
        for (int c = 0; c < CC; c++) if (c == lane) myv = lg[c];
        out[(size_t)r * CC + lane] = myv * inv;
    }
}

// ---------------- launch ----------------------------------------------------
extern "C" void kernel_launch(void* const* d_in, const int* in_sizes, int n_in,
                              void* d_out, int out_size) {
    const float* x       = (const float*)d_in[0];
    const void*  edges   = d_in[1];
    const float* lin_w   = (const float*)d_in[2];
    const float* conv1_w = (const float*)d_in[3];
    const float* conv1_b = (const float*)d_in[4];
    const float* conv2_w = (const float*)d_in[5];
    const float* conv2_b = (const float*)d_in[6];
    const float* mlp1_w  = (const float*)d_in[7];
    const float* mlp1_b  = (const float*)d_in[8];
    const float* bn_g    = (const float*)d_in[9];
    const float* bn_b    = (const float*)d_in[10];
    const float* mlp2_w  = (const float*)d_in[11];
    const float* mlp2_b  = (const float*)d_in[12];
    float*       out     = (float*)d_out;

    float *t = nullptr, *z = nullptr;
    __nv_bfloat16 *ahi = nullptr, *alo = nullptr;
    __nv_bfloat16 *bhi = nullptr, *blo = nullptr, *chi = nullptr, *clo = nullptr;
    cudaGetSymbolAddress((void**)&t,   g_bufB);
    cudaGetSymbolAddress((void**)&z,   g_bufC);
    cudaGetSymbolAddress((void**)&ahi, g_ahi);
    cudaGetSymbolAddress((void**)&alo, g_alo);
    cudaGetSymbolAddress((void**)&bhi, g_bhi);
    cudaGetSymbolAddress((void**)&blo, g_blo);
    cudaGetSymbolAddress((void**)&chi, g_chi);
    cudaGetSymbolAddress((void**)&clo, g_clo);

    cudaFuncSetAttribute(gemm_tc_kernel,
                         cudaFuncAttributeMaxDynamicSharedMemorySize, GEMM_SMEM);

    dim3 ggrid(2, MPAD / 128);   // (2, 391)

    // 1-5: prep so that launch #6 (profiled by ncu -s 5 -c 1) is the encoder GEMM
    detect_dtype_kernel<<<1, 32>>>((const int*)edges);
    zero_kernel<<<256, 256>>>();
    prep_wt_kernel<<<(DD * 512 + 255) / 256, 256>>>(lin_w, GG, 1024);
    {
        long tot = (long)MPAD * 512;
        split_x_kernel<<<(unsigned)((tot + 255) / 256), 256>>>(x);
    }
    count_edges_kernel<<<(EDGES + 255) / 256, 256>>>(edges);

    // 6: encoder GEMM (split output -> bhi/blo)
    gemm_tc_kernel<<<ggrid, 256, GEMM_SMEM>>>(ahi, alo, 1024, nullptr,
                                              bhi, blo, NODES, 1);

    // graph structure (independent of GEMM)
    dinv_kernel<<<(NODES + 255) / 256, 256>>>();
    scan_kernel<<<1, 1024>>>();
    scatter_edges_kernel<<<(EDGES + 255) / 256, 256>>>(edges);

    // conv1
    prep_wt_kernel<<<(DD * 128 + 255) / 256, 256>>>(conv1_w, DD, DD);
    gemm_tc_kernel<<<ggrid, 256, GEMM_SMEM>>>(bhi, blo, DD, t,
                                              nullptr, nullptr, NODES, 0);
    aggregate_kernel<<<NODES, DD>>>(t, conv1_b, chi, clo);

    // conv2
    prep_wt_kernel<<<(DD * 128 + 255) / 256, 256>>>(conv2_w, DD, DD);
    gemm_tc_kernel<<<ggrid, 256, GEMM_SMEM>>>(chi, clo, DD, t,
                                              nullptr, nullptr, NODES, 0);
    aggregate_kernel<<<NODES, DD>>>(t, conv2_b, bhi, blo);

    // mlp1 + BN + relu
    prep_wt_kernel<<<(DD * 128 + 255) / 256, 256>>>(mlp1_w, DD, DD);
    gemm_tc_kernel<<<ggrid, 256, GEMM_SMEM>>>(bhi, blo, DD, t,
                                              nullptr, nullptr, NODES, 0);
    bn_stats_kernel<<<256, DD>>>(t, mlp1_b);
    bn_apply_kernel<<<2048, 256>>>(t, mlp1_b, bn_g, bn_b, z);

    // head
    head_kernel<<<(NODES + 7) / 8, 256>>>(z, mlp2_w, mlp2_b, out);
}